// round 5
// baseline (speedup 1.0000x reference)
#include <cuda_runtime.h>
#include <cuda_fp16.h>

#define NPTS 1600
#define HIDC 64
#define TILE 256
#define NPART 25

__device__ float g_h[NPTS*HIDC];     // pre-norm hidden
__device__ float g_Q[NPTS*HIDC];
__device__ uint2 g_KVT[32*NPTS];     // [(head*4+d2)*NPTS + j] = {K half2, V half2}
__device__ float g_agg[NPTS*HIDC];   // attention output
__device__ float g_o[NPTS*HIDC];     // pre-norm output MLP
__device__ float g_part[NPART*8];    // partial stats
__device__ float g_stats[16];        // [0..3] mu_in [4..7] rs_in [8..11] mu_out [12..15] rs_out

__device__ __forceinline__ float leaky(float x) { return x >= 0.f ? x : 0.2f * x; }

// ---------------- K1: input MLP (pre-norm) ----------------
__global__ __launch_bounds__(256) void k_in_mlp(
    const float* __restrict__ feat,
    const float* __restrict__ w1, const float* __restrict__ b1,
    const float* __restrict__ w2, const float* __restrict__ b2)
{
    __shared__ float t1[16][64];
    int r = threadIdx.x >> 4, s = threadIdx.x & 15;
    int row = blockIdx.x * 16 + r;
    float4 f0 = __ldg((const float4*)&feat[row*16 + 0]);
    float4 f1 = __ldg((const float4*)&feat[row*16 + 4]);
    float4 f2 = __ldg((const float4*)&feat[row*16 + 8]);
    float4 f3 = __ldg((const float4*)&feat[row*16 + 12]);
#pragma unroll
    for (int cc = 0; cc < 4; cc++) {
        int c = s*4 + cc;
        float a = __ldg(&b1[c]);
        const float4* wr = (const float4*)&w1[c*16];
        float4 w0 = __ldg(wr+0), wv1 = __ldg(wr+1), wv2 = __ldg(wr+2), wv3 = __ldg(wr+3);
        a = fmaf(f0.x,w0.x,a);  a = fmaf(f0.y,w0.y,a);  a = fmaf(f0.z,w0.z,a);  a = fmaf(f0.w,w0.w,a);
        a = fmaf(f1.x,wv1.x,a); a = fmaf(f1.y,wv1.y,a); a = fmaf(f1.z,wv1.z,a); a = fmaf(f1.w,wv1.w,a);
        a = fmaf(f2.x,wv2.x,a); a = fmaf(f2.y,wv2.y,a); a = fmaf(f2.z,wv2.z,a); a = fmaf(f2.w,wv2.w,a);
        a = fmaf(f3.x,wv3.x,a); a = fmaf(f3.y,wv3.y,a); a = fmaf(f3.z,wv3.z,a); a = fmaf(f3.w,wv3.w,a);
        t1[r][c] = leaky(a);
    }
    __syncthreads();
#pragma unroll
    for (int cc = 0; cc < 4; cc++) {
        int c = s*4 + cc;
        float a = __ldg(&b2[c]);
#pragma unroll
        for (int k4 = 0; k4 < 16; k4++) {
            float4 w = __ldg((const float4*)&w2[c*64 + k4*4]);
            float4 h = *(const float4*)&t1[r][k4*4];
            a = fmaf(h.x,w.x,a); a = fmaf(h.y,w.y,a); a = fmaf(h.z,w.z,a); a = fmaf(h.w,w.w,a);
        }
        g_h[row*64 + c] = leaky(a);
    }
}

// ---------------- stats: parallel partial + combine ----------------
__global__ __launch_bounds__(256) void k_stats_part(int which)
{
    const float4* src = (const float4*)(which ? g_o : g_h);
    float s[4] = {0,0,0,0}, q[4] = {0,0,0,0};
#pragma unroll
    for (int k = 0; k < 4; k++) {
        int idx = blockIdx.x*1024 + k*256 + threadIdx.x;
        float4 v = src[idx];
        int g = (idx & 15) >> 2;
        s[g] += v.x + v.y + v.z + v.w;
        q[g] += v.x*v.x + v.y*v.y + v.z*v.z + v.w*v.w;
    }
    __shared__ float red[256][8];
#pragma unroll
    for (int g = 0; g < 4; g++) { red[threadIdx.x][g] = s[g]; red[threadIdx.x][4+g] = q[g]; }
    __syncthreads();
    for (int st = 128; st > 0; st >>= 1) {
        if (threadIdx.x < st)
#pragma unroll
            for (int k = 0; k < 8; k++) red[threadIdx.x][k] += red[threadIdx.x + st][k];
        __syncthreads();
    }
    if (threadIdx.x < 8) g_part[blockIdx.x*8 + threadIdx.x] = red[0][threadIdx.x];
}

__global__ __launch_bounds__(32) void k_stats_comb(int which)
{
    int off = which ? 8 : 0;
    int g = threadIdx.x;
    if (g < 4) {
        float s = 0.f, q = 0.f;
        for (int b = 0; b < NPART; b++) { s += g_part[b*8 + g]; q += g_part[b*8 + 4 + g]; }
        const float invn = 1.f / (NPTS * 16.f);
        float mu  = s * invn;
        float var = q * invn - mu*mu;
        g_stats[off + g]     = mu;
        g_stats[off + 4 + g] = rsqrtf(var + 1e-5f);
    }
}

// ---------------- K3: normalize + QKV (K,V fp16 interleaved, transposed) ----------------
__global__ __launch_bounds__(256) void k_qkv(
    const float* __restrict__ wq, const float* __restrict__ bq,
    const float* __restrict__ wk, const float* __restrict__ bk,
    const float* __restrict__ wv, const float* __restrict__ bv,
    const float* __restrict__ gam, const float* __restrict__ bet)
{
    __shared__ float hn[16][64];
    int r = threadIdx.x >> 4, s = threadIdx.x & 15;
    int row = blockIdx.x * 16 + r;
#pragma unroll
    for (int cc = 0; cc < 4; cc++) {
        int c = s*4 + cc;
        int g = c >> 4;
        float x = g_h[row*64 + c];
        float v = (x - g_stats[g]) * g_stats[4+g];
        hn[r][c] = fmaf(v, __ldg(&gam[c]), __ldg(&bet[c]));
    }
    __syncthreads();
    int h   = s >> 1;
    int d2b = (s & 1) * 2;
    const float* Ws[3] = {wq, wk, wv};
    const float* Bs[3] = {bq, bk, bv};
    unsigned int kbits[2];
#pragma unroll
    for (int mtx = 0; mtx < 3; mtx++) {
        const float* W = Ws[mtx]; const float* B = Bs[mtx];
        float av[4];
#pragma unroll
        for (int cc = 0; cc < 4; cc++) {
            int c = s*4 + cc;
            float a = __ldg(&B[c]);
#pragma unroll
            for (int k4 = 0; k4 < 16; k4++) {
                float4 w = __ldg((const float4*)&W[c*64 + k4*4]);
                float4 hh = *(const float4*)&hn[r][k4*4];
                a = fmaf(hh.x,w.x,a); a = fmaf(hh.y,w.y,a); a = fmaf(hh.z,w.z,a); a = fmaf(hh.w,w.w,a);
            }
            av[cc] = a;
        }
        if (mtx == 0) {
#pragma unroll
            for (int cc = 0; cc < 4; cc++) g_Q[row*64 + s*4 + cc] = av[cc];
        } else if (mtx == 1) {
            __half2 k0 = __floats2half2_rn(av[0], av[1]);
            __half2 k1 = __floats2half2_rn(av[2], av[3]);
            kbits[0] = *(unsigned int*)&k0;
            kbits[1] = *(unsigned int*)&k1;
        } else {
            __half2 v0 = __floats2half2_rn(av[0], av[1]);
            __half2 v1 = __floats2half2_rn(av[2], av[3]);
            uint2 kv0, kv1;
            kv0.x = kbits[0]; kv0.y = *(unsigned int*)&v0;
            kv1.x = kbits[1]; kv1.y = *(unsigned int*)&v1;
            g_KVT[(h*4 + d2b    )*NPTS + row] = kv0;
            g_KVT[(h*4 + d2b + 1)*NPTS + row] = kv1;
        }
    }
}

// ---------------- K4: fused pairwise geometry + conv + attention ----------------
__device__ __forceinline__ void attn_body(
    int j, const uint4 fu, const float wgt, const uint2* __restrict__ KVTb,
    const __half2* qh2, const __half2* w2h, const __half2* b2h,
    float* acc, float& denom)
{
    uint2 kva = __ldg(&KVTb[j]);
    uint2 kvb = __ldg(&KVTb[NPTS + j]);
    uint2 kvc = __ldg(&KVTb[2*NPTS + j]);
    uint2 kvd = __ldg(&KVTb[3*NPTS + j]);
    __half2 ka = *(const __half2*)&kva.x, kb = *(const __half2*)&kvb.x;
    __half2 kc = *(const __half2*)&kvc.x, kd = *(const __half2*)&kvd.x;
    __half2 t0 = __hmul2(qh2[0], ka); t0 = __hfma2(qh2[1], kb, t0);
    __half2 t1 = __hmul2(qh2[2], kc); t1 = __hfma2(qh2[3], kd, t1);
    float2 sf = __half22float2(__hadd2(t0, t1));
    float e = __expf(sf.x + sf.y);
    denom += e;
    float ew = e * wgt;

    __half2 h01 = *(const __half2*)&fu.x, h23 = *(const __half2*)&fu.y;
    __half2 h45 = *(const __half2*)&fu.z, h67 = *(const __half2*)&fu.w;
    __half2 fb8[8];
    fb8[0] = __low2half2(h01); fb8[1] = __high2half2(h01);
    fb8[2] = __low2half2(h23); fb8[3] = __high2half2(h23);
    fb8[4] = __low2half2(h45); fb8[5] = __high2half2(h45);
    fb8[6] = __low2half2(h67); fb8[7] = __high2half2(h67);
    __half2 a0 = b2h[0], a1 = b2h[1], a2 = b2h[2], a3 = b2h[3];
#pragma unroll
    for (int k = 0; k < 8; k++) {
        a0 = __hfma2(fb8[k], w2h[k],    a0);
        a1 = __hfma2(fb8[k], w2h[8+k],  a1);
        a2 = __hfma2(fb8[k], w2h[16+k], a2);
        a3 = __hfma2(fb8[k], w2h[24+k], a3);
    }
    const __half2 zero2 = __float2half2_rn(0.f);
    a0 = __hmax2(a0, zero2); a1 = __hmax2(a1, zero2);
    a2 = __hmax2(a2, zero2); a3 = __hmax2(a3, zero2);
    {
        float2 p = __half22float2(__hmul2(a0, *(const __half2*)&kva.y));
        acc[0] = fmaf(ew, p.x, acc[0]); acc[1] = fmaf(ew, p.y, acc[1]);
    }
    {
        float2 p = __half22float2(__hmul2(a1, *(const __half2*)&kvb.y));
        acc[2] = fmaf(ew, p.x, acc[2]); acc[3] = fmaf(ew, p.y, acc[3]);
    }
    {
        float2 p = __half22float2(__hmul2(a2, *(const __half2*)&kvc.y));
        acc[4] = fmaf(ew, p.x, acc[4]); acc[5] = fmaf(ew, p.y, acc[5]);
    }
    {
        float2 p = __half22float2(__hmul2(a3, *(const __half2*)&kvd.y));
        acc[6] = fmaf(ew, p.x, acc[6]); acc[7] = fmaf(ew, p.y, acc[7]);
    }
}

__global__ __launch_bounds__(256, 2) void k_attn(
    const float* __restrict__ points, const float* __restrict__ nuv,
    const float* __restrict__ cw1, const float* __restrict__ cb1,
    const float* __restrict__ cw2, const float* __restrict__ cb2,
    const float* __restrict__ rls, const float* __restrict__ ra,
    const float* __restrict__ rb, const float* __restrict__ rc)
{
    const float INVS  = 0.11785113019775793f;   // 1/(sqrt(2)*6)
    const float SCALE = 0.3535533905932738f;    // 1/sqrt(8)
    int i = blockIdx.x;
    int tid = threadIdx.x, warp = tid >> 5, lane = tid & 31;

    __shared__ uint4 sF1h[TILE];     // 8 x fp16 F1 values, one LDS.128 per j
    __shared__ float sWgt[TILE];
    __shared__ float sQ[64];
    __shared__ float sNuv[9], sPi[3];
    __shared__ float sw1[64], sb1[8], sra[32], srb[4], src[8], sInv2s2;

    if (tid < 64) { sw1[tid] = __ldg(&cw1[tid]); sQ[tid] = g_Q[i*64 + tid]; }
    if (tid < 8)  { sb1[tid] = __ldg(&cb1[tid]); src[tid] = __ldg(&rc[tid]); }
    if (tid < 32) sra[tid] = __ldg(&ra[tid]);
    if (tid < 4)  srb[tid] = __ldg(&rb[tid]);
    if (tid < 9)  sNuv[tid] = nuv[i*9 + tid];
    if (tid < 3)  sPi[tid]  = points[i*3 + tid];
    if (tid == 0) { float sg = fmaxf(__expf(__ldg(&rls[0])), 1e-6f); sInv2s2 = 0.5f/(sg*sg); }
    __syncthreads();

    // head-private: conv_w2 half2 c-pair packed, bias, Q half2 with scale folded
    __half2 w2h[32], b2h[4], qh2[4];
#pragma unroll
    for (int cp = 0; cp < 4; cp++) {
        b2h[cp] = __floats2half2_rn(__ldg(&cb2[warp*8 + 2*cp]), __ldg(&cb2[warp*8 + 2*cp + 1]));
        qh2[cp] = __floats2half2_rn(sQ[warp*8 + 2*cp] * SCALE, sQ[warp*8 + 2*cp + 1] * SCALE);
#pragma unroll
        for (int k = 0; k < 8; k++)
            w2h[cp*8 + k] = __floats2half2_rn(__ldg(&cw2[(warp*8 + 2*cp)*8 + k]),
                                              __ldg(&cw2[(warp*8 + 2*cp + 1)*8 + k]));
    }
    float denom = 0.f;
    float acc[8];
#pragma unroll
    for (int c = 0; c < 8; c++) acc[c] = 0.f;

    const uint2* KVTb = &g_KVT[warp*4*NPTS];

    for (int tb = 0; tb < NPTS; tb += TILE) {
        int j = tb + tid;
        if (j < NPTS) {
            float dx = (points[j*3+0] - sPi[0]) * INVS;
            float dy = (points[j*3+1] - sPi[1]) * INVS;
            float dz = (points[j*3+2] - sPi[2]) * INVS;
            float ndot = sNuv[0]*nuv[j*9+0] + sNuv[1]*nuv[j*9+1] + sNuv[2]*nuv[j*9+2];
            float u = 2.f - ndot;
            float d2 = (dx*dx + dy*dy + dz*dz) * u * u;
            float t = 1.f / (1.f + d2 * (1.f/3.f));
            sWgt[tid] = t*t*t;
            float bd = sqrtf(d2);
            float X[8];
            X[0] = sNuv[0]*dx + sNuv[1]*dy + sNuv[2]*dz;
            X[1] = sNuv[3]*dx + sNuv[4]*dy + sNuv[5]*dz;
            X[2] = sNuv[6]*dx + sNuv[7]*dy + sNuv[8]*dz;
            X[3] = ndot;
            float rp0 = srb[0], rp1 = srb[1], rp2 = srb[2], rp3 = srb[3];
#pragma unroll
            for (int r = 0; r < 8; r++) {
                float dd = bd - src[r];
                float e = __expf(-dd*dd * sInv2s2);
                rp0 = fmaf(e, sra[0*8+r], rp0);
                rp1 = fmaf(e, sra[1*8+r], rp1);
                rp2 = fmaf(e, sra[2*8+r], rp2);
                rp3 = fmaf(e, sra[3*8+r], rp3);
            }
            X[4] = rp0; X[5] = rp1; X[6] = rp2; X[7] = rp3;
            float F[8];
#pragma unroll
            for (int c = 0; c < 8; c++) {
                float a = sb1[c];
#pragma unroll
                for (int k = 0; k < 8; k++) a = fmaf(X[k], sw1[c*8+k], a);
                F[c] = fmaxf(a, 0.f);
            }
            uint4 pkv;
            __half2 h01 = __floats2half2_rn(F[0], F[1]);
            __half2 h23 = __floats2half2_rn(F[2], F[3]);
            __half2 h45 = __floats2half2_rn(F[4], F[5]);
            __half2 h67 = __floats2half2_rn(F[6], F[7]);
            pkv.x = *(unsigned int*)&h01; pkv.y = *(unsigned int*)&h23;
            pkv.z = *(unsigned int*)&h45; pkv.w = *(unsigned int*)&h67;
            sF1h[tid] = pkv;
        }
        __syncthreads();
        int cnt = min(TILE, NPTS - tb);
        if (cnt == TILE) {
#pragma unroll 4
            for (int it = 0; it < TILE/32; it++) {
                int jj = it*32 + lane;
                attn_body(tb + jj, sF1h[jj], sWgt[jj], KVTb, qh2, w2h, b2h, acc, denom);
            }
        } else {
#pragma unroll 2
            for (int it = 0; it < 2; it++) {
                int jj = it*32 + lane;
                if (jj < cnt)
                    attn_body(tb + jj, sF1h[jj], sWgt[jj], KVTb, qh2, w2h, b2h, acc, denom);
            }
        }
        __syncthreads();
    }
    // warp reductions
#pragma unroll
    for (int o = 16; o > 0; o >>= 1) denom += __shfl_xor_sync(0xffffffffu, denom, o);
#pragma unroll
    for (int c = 0; c < 8; c++)
#pragma unroll
        for (int o = 16; o > 0; o >>= 1) acc[c] += __shfl_xor_sync(0xffffffffu, acc[c], o);
    if (lane == 0) {
        float inv = 1.f / denom;
#pragma unroll
        for (int c = 0; c < 8; c++) g_agg[i*64 + warp*8 + c] = acc[c] * inv;
    }
}

// ---------------- K5: output MLP (pre-norm) ----------------
__global__ __launch_bounds__(256) void k_out_mlp(
    const float* __restrict__ w1, const float* __restrict__ b1,
    const float* __restrict__ w2, const float* __restrict__ b2)
{
    __shared__ float a0[16][64];
    __shared__ float t1[16][64];
    int r = threadIdx.x >> 4, s = threadIdx.x & 15;
    int row = blockIdx.x * 16 + r;
#pragma unroll
    for (int cc = 0; cc < 4; cc++) {
        int c = s*4 + cc;
        a0[r][c] = g_agg[row*64 + c];
    }
    __syncthreads();
#pragma unroll
    for (int cc = 0; cc < 4; cc++) {
        int c = s*4 + cc;
        float a = __ldg(&b1[c]);
#pragma unroll
        for (int k4 = 0; k4 < 16; k4++) {
            float4 w = __ldg((const float4*)&w1[c*64 + k4*4]);
            float4 h = *(const float4*)&a0[r][k4*4];
            a = fmaf(h.x,w.x,a); a = fmaf(h.y,w.y,a); a = fmaf(h.z,w.z,a); a = fmaf(h.w,w.w,a);
        }
        t1[r][c] = leaky(a);
    }
    __syncthreads();
#pragma unroll
    for (int cc = 0; cc < 4; cc++) {
        int c = s*4 + cc;
        float a = __ldg(&b2[c]);
#pragma unroll
        for (int k4 = 0; k4 < 16; k4++) {
            float4 w = __ldg((const float4*)&w2[c*64 + k4*4]);
            float4 h = *(const float4*)&t1[r][k4*4];
            a = fmaf(h.x,w.x,a); a = fmaf(h.y,w.y,a); a = fmaf(h.z,w.z,a); a = fmaf(h.w,w.w,a);
        }
        g_o[row*64 + c] = leaky(a);
    }
}

// ---------------- K7: final norm + residual ----------------
__global__ __launch_bounds__(256) void k_finalize(
    const float* __restrict__ feat,
    const float* __restrict__ gam, const float* __restrict__ bet,
    const float* __restrict__ wres, const float* __restrict__ bres,
    float* __restrict__ out)
{
    int idx = blockIdx.x * 256 + threadIdx.x;
    int row = idx >> 6, c = idx & 63, g = c >> 4;
    float x = (g_o[idx] - g_stats[8+g]) * g_stats[12+g];
    x = fmaf(x, __ldg(&gam[c]), __ldg(&bet[c]));
    float a = __ldg(&bres[c]);
#pragma unroll
    for (int k4 = 0; k4 < 4; k4++) {
        float4 f = __ldg((const float4*)&feat[row*16 + k4*4]);
        float4 w = __ldg((const float4*)&wres[c*16 + k4*4]);
        a = fmaf(f.x,w.x,a); a = fmaf(f.y,w.y,a); a = fmaf(f.z,w.z,a); a = fmaf(f.w,w.w,a);
    }
    out[idx] = x + a;
}

extern "C" void kernel_launch(void* const* d_in, const int* in_sizes, int n_in,
                              void* d_out, int out_size)
{
    const float* points   = (const float*)d_in[0];
    const float* nuv      = (const float*)d_in[1];
    const float* features = (const float*)d_in[2];
    const float* w_in1    = (const float*)d_in[3];
    const float* b_in1    = (const float*)d_in[4];
    const float* w_in2    = (const float*)d_in[5];
    const float* b_in2    = (const float*)d_in[6];
    const float* g_in     = (const float*)d_in[7];
    const float* be_in    = (const float*)d_in[8];
    const float* wq       = (const float*)d_in[9];
    const float* bq       = (const float*)d_in[10];
    const float* wk       = (const float*)d_in[11];
    const float* bk       = (const float*)d_in[12];
    const float* wv       = (const float*)d_in[13];
    const float* bv       = (const float*)d_in[14];
    const float* conv_w1  = (const float*)d_in[15];
    const float* conv_b1  = (const float*)d_in[16];
    const float* conv_w2  = (const float*)d_in[17];
    const float* conv_b2  = (const float*)d_in[18];
    const float* rls      = (const float*)d_in[19];
    const float* rbf_a    = (const float*)d_in[20];
    const float* rbf_b    = (const float*)d_in[21];
    const float* rbf_c    = (const float*)d_in[22];
    const float* w_o1     = (const float*)d_in[23];
    const float* b_o1     = (const float*)d_in[24];
    const float* w_o2     = (const float*)d_in[25];
    const float* b_o2     = (const float*)d_in[26];
    const float* g_out    = (const float*)d_in[27];
    const float* be_out   = (const float*)d_in[28];
    const float* w_res    = (const float*)d_in[29];
    const float* b_res    = (const float*)d_in[30];

    k_in_mlp<<<NPTS/16, 256>>>(features, w_in1, b_in1, w_in2, b_in2);
    k_stats_part<<<NPART, 256>>>(0);
    k_stats_comb<<<1, 32>>>(0);
    k_qkv<<<NPTS/16, 256>>>(wq, bq, wk, bk, wv, bv, g_in, be_in);
    k_attn<<<NPTS, 256>>>(points, nuv, conv_w1, conv_b1, conv_w2, conv_b2,
                          rls, rbf_a, rbf_b, rbf_c);
    k_out_mlp<<<NPTS/16, 256>>>(w_o1, b_o1, w_o2, b_o2);
    k_stats_part<<<NPART, 256>>>(1);
    k_stats_comb<<<1, 32>>>(1);
    k_finalize<<<NPTS*64/256, 256>>>(features, g_out, be_out, w_res, b_res, (float*)d_out);
}

// round 6
// speedup vs baseline: 1.3558x; 1.3558x over previous
#include <cuda_runtime.h>
#include <cuda_fp16.h>

#define NPTS 1600
#define HIDC 64
#define TILE 256
#define NPART 25

__device__ float g_h[NPTS*HIDC];     // pre-norm hidden
__device__ float g_Q[NPTS*HIDC];
__device__ uint2 g_KVT[32*NPTS];     // [(head*4+d2)*NPTS + j] = {K half2, V half2}
__device__ float g_agg[NPTS*HIDC];   // attention output
__device__ float g_o[NPTS*HIDC];     // pre-norm output MLP
__device__ float g_part[NPART*8];    // partial stats
__device__ float g_stats[16];        // [0..3] mu_in [4..7] rs_in [8..11] mu_out [12..15] rs_out

__device__ __forceinline__ float leaky(float x) { return x >= 0.f ? x : 0.2f * x; }

// ---------------- K1: input MLP (pre-norm), smem-staged weights ----------------
// 256 threads = 4 rows x 64 channels; grid 400
__global__ __launch_bounds__(256) void k_in_mlp(
    const float* __restrict__ feat,
    const float* __restrict__ w1, const float* __restrict__ b1,
    const float* __restrict__ w2, const float* __restrict__ b2)
{
    __shared__ float sf[4][16];
    __shared__ float t1[4][68];
    __shared__ float wt[64*65];
    int tid = threadIdx.x;
    int r = tid >> 6, c = tid & 63;
    int row = blockIdx.x*4 + r;

    if (tid < 64) sf[tid >> 4][tid & 15] = feat[blockIdx.x*64 + tid];
    // stage w1^T : wt[k*65+c] = w1[c*16+k]
#pragma unroll
    for (int i = 0; i < 4; i++) {
        int idx = i*256 + tid;
        int cc = idx >> 4, kk = idx & 15;
        wt[kk*65 + cc] = w1[idx];
    }
    __syncthreads();
    float a = __ldg(&b1[c]);
#pragma unroll
    for (int k = 0; k < 16; k++) a = fmaf(sf[r][k], wt[k*65 + c], a);
    t1[r][c] = leaky(a);
    __syncthreads();
    // stage w2^T
#pragma unroll
    for (int i = 0; i < 16; i++) {
        int idx = i*256 + tid;
        int cc = idx >> 6, kk = idx & 63;
        wt[kk*65 + cc] = w2[idx];
    }
    __syncthreads();
    float a2 = __ldg(&b2[c]);
#pragma unroll
    for (int k = 0; k < 64; k += 4) {
        float4 h4 = *(const float4*)&t1[r][k];
        a2 = fmaf(h4.x, wt[(k  )*65 + c], a2);
        a2 = fmaf(h4.y, wt[(k+1)*65 + c], a2);
        a2 = fmaf(h4.z, wt[(k+2)*65 + c], a2);
        a2 = fmaf(h4.w, wt[(k+3)*65 + c], a2);
    }
    g_h[row*64 + c] = leaky(a2);
}

// ---------------- stats: parallel partial + combine ----------------
__global__ __launch_bounds__(256) void k_stats_part(int which)
{
    const float4* src = (const float4*)(which ? g_o : g_h);
    float s[4] = {0,0,0,0}, q[4] = {0,0,0,0};
#pragma unroll
    for (int k = 0; k < 4; k++) {
        int idx = blockIdx.x*1024 + k*256 + threadIdx.x;
        float4 v = src[idx];
        int g = (idx & 15) >> 2;
        s[g] += v.x + v.y + v.z + v.w;
        q[g] += v.x*v.x + v.y*v.y + v.z*v.z + v.w*v.w;
    }
    __shared__ float red[256][8];
#pragma unroll
    for (int g = 0; g < 4; g++) { red[threadIdx.x][g] = s[g]; red[threadIdx.x][4+g] = q[g]; }
    __syncthreads();
    for (int st = 128; st > 0; st >>= 1) {
        if (threadIdx.x < st)
#pragma unroll
            for (int k = 0; k < 8; k++) red[threadIdx.x][k] += red[threadIdx.x + st][k];
        __syncthreads();
    }
    if (threadIdx.x < 8) g_part[blockIdx.x*8 + threadIdx.x] = red[0][threadIdx.x];
}

__global__ __launch_bounds__(32) void k_stats_comb(int which)
{
    int off = which ? 8 : 0;
    int g = threadIdx.x;
    if (g < 4) {
        float s = 0.f, q = 0.f;
        for (int b = 0; b < NPART; b++) { s += g_part[b*8 + g]; q += g_part[b*8 + 4 + g]; }
        const float invn = 1.f / (NPTS * 16.f);
        float mu  = s * invn;
        float var = q * invn - mu*mu;
        g_stats[off + g]     = mu;
        g_stats[off + 4 + g] = rsqrtf(var + 1e-5f);
    }
}

// ---------------- K3: normalize + QKV (smem-staged; K,V fp16 interleaved transposed) ----------------
// 256 threads = 4 rows x 64 channels; grid 400
__global__ __launch_bounds__(256) void k_qkv(
    const float* __restrict__ wq, const float* __restrict__ bq,
    const float* __restrict__ wk, const float* __restrict__ bk,
    const float* __restrict__ wv, const float* __restrict__ bv,
    const float* __restrict__ gam, const float* __restrict__ bet)
{
    __shared__ float hn[4][68];
    __shared__ float wt[64*65];
    __shared__ float sK[4][64];
    __shared__ float sV[4][64];
    int tid = threadIdx.x;
    int r = tid >> 6, c = tid & 63;
    int row = blockIdx.x*4 + r;

    {
        int g = c >> 4;
        float x = g_h[row*64 + c];
        float v = (x - g_stats[g]) * g_stats[4+g];
        hn[r][c] = fmaf(v, __ldg(&gam[c]), __ldg(&bet[c]));
    }

    const float* Ws[3] = {wq, wk, wv};
    const float* Bs[3] = {bq, bk, bv};
#pragma unroll
    for (int mtx = 0; mtx < 3; mtx++) {
        __syncthreads();   // protect wt from previous compute readers
#pragma unroll
        for (int i = 0; i < 16; i++) {
            int idx = i*256 + tid;
            int cc = idx >> 6, kk = idx & 63;
            wt[kk*65 + cc] = Ws[mtx][idx];
        }
        __syncthreads();
        float a = __ldg(&Bs[mtx][c]);
#pragma unroll
        for (int k = 0; k < 64; k += 4) {
            float4 h4 = *(const float4*)&hn[r][k];
            a = fmaf(h4.x, wt[(k  )*65 + c], a);
            a = fmaf(h4.y, wt[(k+1)*65 + c], a);
            a = fmaf(h4.z, wt[(k+2)*65 + c], a);
            a = fmaf(h4.w, wt[(k+3)*65 + c], a);
        }
        if (mtx == 0)      g_Q[row*64 + c] = a;
        else if (mtx == 1) sK[r][c] = a;
        else               sV[r][c] = a;
    }
    __syncthreads();
    // pack interleaved KV: 128 threads = 4 rows x 32 channel-pairs; index = cp*NPTS + row
    if (tid < 128) {
        int rr = tid >> 5, cp = tid & 31;
        int rw = blockIdx.x*4 + rr;
        __half2 kh = __floats2half2_rn(sK[rr][2*cp], sK[rr][2*cp+1]);
        __half2 vh = __floats2half2_rn(sV[rr][2*cp], sV[rr][2*cp+1]);
        uint2 kv;
        kv.x = *(unsigned int*)&kh;
        kv.y = *(unsigned int*)&vh;
        g_KVT[cp*NPTS + rw] = kv;
    }
}

// ---------------- K4: fused pairwise geometry + conv + attention ----------------
__device__ __forceinline__ void attn_body(
    int j, const uint4 fu, const float wgt, const uint2* __restrict__ KVTb,
    const __half2* qh2, const __half2* w2h, const __half2* b2h,
    float* acc, float& denom)
{
    uint2 kva = __ldg(&KVTb[j]);
    uint2 kvb = __ldg(&KVTb[NPTS + j]);
    uint2 kvc = __ldg(&KVTb[2*NPTS + j]);
    uint2 kvd = __ldg(&KVTb[3*NPTS + j]);
    __half2 ka = *(const __half2*)&kva.x, kb = *(const __half2*)&kvb.x;
    __half2 kc = *(const __half2*)&kvc.x, kd = *(const __half2*)&kvd.x;
    __half2 t0 = __hmul2(qh2[0], ka); t0 = __hfma2(qh2[1], kb, t0);
    __half2 t1 = __hmul2(qh2[2], kc); t1 = __hfma2(qh2[3], kd, t1);
    float2 sf = __half22float2(__hadd2(t0, t1));
    float e = __expf(sf.x + sf.y);
    denom += e;
    float ew = e * wgt;

    __half2 h01 = *(const __half2*)&fu.x, h23 = *(const __half2*)&fu.y;
    __half2 h45 = *(const __half2*)&fu.z, h67 = *(const __half2*)&fu.w;
    __half2 fb8[8];
    fb8[0] = __low2half2(h01); fb8[1] = __high2half2(h01);
    fb8[2] = __low2half2(h23); fb8[3] = __high2half2(h23);
    fb8[4] = __low2half2(h45); fb8[5] = __high2half2(h45);
    fb8[6] = __low2half2(h67); fb8[7] = __high2half2(h67);
    __half2 a0 = b2h[0], a1 = b2h[1], a2 = b2h[2], a3 = b2h[3];
#pragma unroll
    for (int k = 0; k < 8; k++) {
        a0 = __hfma2(fb8[k], w2h[k],    a0);
        a1 = __hfma2(fb8[k], w2h[8+k],  a1);
        a2 = __hfma2(fb8[k], w2h[16+k], a2);
        a3 = __hfma2(fb8[k], w2h[24+k], a3);
    }
    const __half2 zero2 = __float2half2_rn(0.f);
    a0 = __hmax2(a0, zero2); a1 = __hmax2(a1, zero2);
    a2 = __hmax2(a2, zero2); a3 = __hmax2(a3, zero2);
    {
        float2 p = __half22float2(__hmul2(a0, *(const __half2*)&kva.y));
        acc[0] = fmaf(ew, p.x, acc[0]); acc[1] = fmaf(ew, p.y, acc[1]);
    }
    {
        float2 p = __half22float2(__hmul2(a1, *(const __half2*)&kvb.y));
        acc[2] = fmaf(ew, p.x, acc[2]); acc[3] = fmaf(ew, p.y, acc[3]);
    }
    {
        float2 p = __half22float2(__hmul2(a2, *(const __half2*)&kvc.y));
        acc[4] = fmaf(ew, p.x, acc[4]); acc[5] = fmaf(ew, p.y, acc[5]);
    }
    {
        float2 p = __half22float2(__hmul2(a3, *(const __half2*)&kvd.y));
        acc[6] = fmaf(ew, p.x, acc[6]); acc[7] = fmaf(ew, p.y, acc[7]);
    }
}

__global__ __launch_bounds__(256, 2) void k_attn(
    const float* __restrict__ points, const float* __restrict__ nuv,
    const float* __restrict__ cw1, const float* __restrict__ cb1,
    const float* __restrict__ cw2, const float* __restrict__ cb2,
    const float* __restrict__ rls, const float* __restrict__ ra,
    const float* __restrict__ rb, const float* __restrict__ rc)
{
    const float INVS  = 0.11785113019775793f;   // 1/(sqrt(2)*6)
    const float SCALE = 0.3535533905932738f;    // 1/sqrt(8)
    int i = blockIdx.x;
    int tid = threadIdx.x, warp = tid >> 5, lane = tid & 31;

    __shared__ uint4 sF1h[TILE];     // 8 x fp16 F1 values, one LDS.128 per j
    __shared__ float sWgt[TILE];
    __shared__ float sQ[64];
    __shared__ float sNuv[9], sPi[3];
    __shared__ float sw1[64], sb1[8], sra[32], srb[4], src[8], sInv2s2;

    if (tid < 64) { sw1[tid] = __ldg(&cw1[tid]); sQ[tid] = g_Q[i*64 + tid]; }
    if (tid < 8)  { sb1[tid] = __ldg(&cb1[tid]); src[tid] = __ldg(&rc[tid]); }
    if (tid < 32) sra[tid] = __ldg(&ra[tid]);
    if (tid < 4)  srb[tid] = __ldg(&rb[tid]);
    if (tid < 9)  sNuv[tid] = nuv[i*9 + tid];
    if (tid < 3)  sPi[tid]  = points[i*3 + tid];
    if (tid == 0) { float sg = fmaxf(__expf(__ldg(&rls[0])), 1e-6f); sInv2s2 = 0.5f/(sg*sg); }
    __syncthreads();

    // head-private: conv_w2 half2 c-pair packed, bias, Q half2 with scale folded
    __half2 w2h[32], b2h[4], qh2[4];
#pragma unroll
    for (int cp = 0; cp < 4; cp++) {
        b2h[cp] = __floats2half2_rn(__ldg(&cb2[warp*8 + 2*cp]), __ldg(&cb2[warp*8 + 2*cp + 1]));
        qh2[cp] = __floats2half2_rn(sQ[warp*8 + 2*cp] * SCALE, sQ[warp*8 + 2*cp + 1] * SCALE);
#pragma unroll
        for (int k = 0; k < 8; k++)
            w2h[cp*8 + k] = __floats2half2_rn(__ldg(&cw2[(warp*8 + 2*cp)*8 + k]),
                                              __ldg(&cw2[(warp*8 + 2*cp + 1)*8 + k]));
    }
    float denom = 0.f;
    float acc[8];
#pragma unroll
    for (int c = 0; c < 8; c++) acc[c] = 0.f;

    const uint2* KVTb = &g_KVT[warp*4*NPTS];

    for (int tb = 0; tb < NPTS; tb += TILE) {
        int j = tb + tid;
        if (j < NPTS) {
            float dx = (points[j*3+0] - sPi[0]) * INVS;
            float dy = (points[j*3+1] - sPi[1]) * INVS;
            float dz = (points[j*3+2] - sPi[2]) * INVS;
            float ndot = sNuv[0]*nuv[j*9+0] + sNuv[1]*nuv[j*9+1] + sNuv[2]*nuv[j*9+2];
            float u = 2.f - ndot;
            float d2 = (dx*dx + dy*dy + dz*dz) * u * u;
            float t = 1.f / (1.f + d2 * (1.f/3.f));
            sWgt[tid] = t*t*t;
            float bd = sqrtf(d2);
            float X[8];
            X[0] = sNuv[0]*dx + sNuv[1]*dy + sNuv[2]*dz;
            X[1] = sNuv[3]*dx + sNuv[4]*dy + sNuv[5]*dz;
            X[2] = sNuv[6]*dx + sNuv[7]*dy + sNuv[8]*dz;
            X[3] = ndot;
            float rp0 = srb[0], rp1 = srb[1], rp2 = srb[2], rp3 = srb[3];
#pragma unroll
            for (int r = 0; r < 8; r++) {
                float dd = bd - src[r];
                float e = __expf(-dd*dd * sInv2s2);
                rp0 = fmaf(e, sra[0*8+r], rp0);
                rp1 = fmaf(e, sra[1*8+r], rp1);
                rp2 = fmaf(e, sra[2*8+r], rp2);
                rp3 = fmaf(e, sra[3*8+r], rp3);
            }
            X[4] = rp0; X[5] = rp1; X[6] = rp2; X[7] = rp3;
            float F[8];
#pragma unroll
            for (int c = 0; c < 8; c++) {
                float a = sb1[c];
#pragma unroll
                for (int k = 0; k < 8; k++) a = fmaf(X[k], sw1[c*8+k], a);
                F[c] = fmaxf(a, 0.f);
            }
            uint4 pkv;
            __half2 h01 = __floats2half2_rn(F[0], F[1]);
            __half2 h23 = __floats2half2_rn(F[2], F[3]);
            __half2 h45 = __floats2half2_rn(F[4], F[5]);
            __half2 h67 = __floats2half2_rn(F[6], F[7]);
            pkv.x = *(unsigned int*)&h01; pkv.y = *(unsigned int*)&h23;
            pkv.z = *(unsigned int*)&h45; pkv.w = *(unsigned int*)&h67;
            sF1h[tid] = pkv;
        }
        __syncthreads();
        int cnt = min(TILE, NPTS - tb);
        if (cnt == TILE) {
#pragma unroll 4
            for (int it = 0; it < TILE/32; it++) {
                int jj = it*32 + lane;
                attn_body(tb + jj, sF1h[jj], sWgt[jj], KVTb, qh2, w2h, b2h, acc, denom);
            }
        } else {
#pragma unroll 2
            for (int it = 0; it < 2; it++) {
                int jj = it*32 + lane;
                if (jj < cnt)
                    attn_body(tb + jj, sF1h[jj], sWgt[jj], KVTb, qh2, w2h, b2h, acc, denom);
            }
        }
        __syncthreads();
    }
    // warp reductions
#pragma unroll
    for (int o = 16; o > 0; o >>= 1) denom += __shfl_xor_sync(0xffffffffu, denom, o);
#pragma unroll
    for (int c = 0; c < 8; c++)
#pragma unroll
        for (int o = 16; o > 0; o >>= 1) acc[c] += __shfl_xor_sync(0xffffffffu, acc[c], o);
    if (lane == 0) {
        float inv = 1.f / denom;
#pragma unroll
        for (int c = 0; c < 8; c++) g_agg[i*64 + warp*8 + c] = acc[c] * inv;
    }
}

// ---------------- K5: output MLP (pre-norm), smem-staged ----------------
// 256 threads = 4 rows x 64 channels; grid 400
__global__ __launch_bounds__(256) void k_out_mlp(
    const float* __restrict__ w1, const float* __restrict__ b1,
    const float* __restrict__ w2, const float* __restrict__ b2)
{
    __shared__ float a0[4][68];
    __shared__ float t1[4][68];
    __shared__ float wt[64*65];
    int tid = threadIdx.x;
    int r = tid >> 6, c = tid & 63;
    int row = blockIdx.x*4 + r;

    a0[r][c] = g_agg[row*64 + c];
    // stage w1^T
#pragma unroll
    for (int i = 0; i < 16; i++) {
        int idx = i*256 + tid;
        int cc = idx >> 6, kk = idx & 63;
        wt[kk*65 + cc] = w1[idx];
    }
    __syncthreads();
    float a = __ldg(&b1[c]);
#pragma unroll
    for (int k = 0; k < 64; k += 4) {
        float4 h4 = *(const float4*)&a0[r][k];
        a = fmaf(h4.x, wt[(k  )*65 + c], a);
        a = fmaf(h4.y, wt[(k+1)*65 + c], a);
        a = fmaf(h4.z, wt[(k+2)*65 + c], a);
        a = fmaf(h4.w, wt[(k+3)*65 + c], a);
    }
    t1[r][c] = leaky(a);
    __syncthreads();
    // stage w2^T
#pragma unroll
    for (int i = 0; i < 16; i++) {
        int idx = i*256 + tid;
        int cc = idx >> 6, kk = idx & 63;
        wt[kk*65 + cc] = w2[idx];
    }
    __syncthreads();
    float a2 = __ldg(&b2[c]);
#pragma unroll
    for (int k = 0; k < 64; k += 4) {
        float4 h4 = *(const float4*)&t1[r][k];
        a2 = fmaf(h4.x, wt[(k  )*65 + c], a2);
        a2 = fmaf(h4.y, wt[(k+1)*65 + c], a2);
        a2 = fmaf(h4.z, wt[(k+2)*65 + c], a2);
        a2 = fmaf(h4.w, wt[(k+3)*65 + c], a2);
    }
    g_o[row*64 + c] = leaky(a2);
}

// ---------------- K7: final norm + residual ----------------
__global__ __launch_bounds__(256) void k_finalize(
    const float* __restrict__ feat,
    const float* __restrict__ gam, const float* __restrict__ bet,
    const float* __restrict__ wres, const float* __restrict__ bres,
    float* __restrict__ out)
{
    int idx = blockIdx.x * 256 + threadIdx.x;
    int row = idx >> 6, c = idx & 63, g = c >> 4;
    float x = (g_o[idx] - g_stats[8+g]) * g_stats[12+g];
    x = fmaf(x, __ldg(&gam[c]), __ldg(&bet[c]));
    float a = __ldg(&bres[c]);
#pragma unroll
    for (int k4 = 0; k4 < 4; k4++) {
        float4 f = __ldg((const float4*)&feat[row*16 + k4*4]);
        float4 w = __ldg((const float4*)&wres[c*16 + k4*4]);
        a = fmaf(f.x,w.x,a); a = fmaf(f.y,w.y,a); a = fmaf(f.z,w.z,a); a = fmaf(f.w,w.w,a);
    }
    out[idx] = x + a;
}

extern "C" void kernel_launch(void* const* d_in, const int* in_sizes, int n_in,
                              void* d_out, int out_size)
{
    const float* points   = (const float*)d_in[0];
    const float* nuv      = (const float*)d_in[1];
    const float* features = (const float*)d_in[2];
    const float* w_in1    = (const float*)d_in[3];
    const float* b_in1    = (const float*)d_in[4];
    const float* w_in2    = (const float*)d_in[5];
    const float* b_in2    = (const float*)d_in[6];
    const float* g_in     = (const float*)d_in[7];
    const float* be_in    = (const float*)d_in[8];
    const float* wq       = (const float*)d_in[9];
    const float* bq       = (const float*)d_in[10];
    const float* wk       = (const float*)d_in[11];
    const float* bk       = (const float*)d_in[12];
    const float* wv       = (const float*)d_in[13];
    const float* bv       = (const float*)d_in[14];
    const float* conv_w1  = (const float*)d_in[15];
    const float* conv_b1  = (const float*)d_in[16];
    const float* conv_w2  = (const float*)d_in[17];
    const float* conv_b2  = (const float*)d_in[18];
    const float* rls      = (const float*)d_in[19];
    const float* rbf_a    = (const float*)d_in[20];
    const float* rbf_b    = (const float*)d_in[21];
    const float* rbf_c    = (const float*)d_in[22];
    const float* w_o1     = (const float*)d_in[23];
    const float* b_o1     = (const float*)d_in[24];
    const float* w_o2     = (const float*)d_in[25];
    const float* b_o2     = (const float*)d_in[26];
    const float* g_out    = (const float*)d_in[27];
    const float* be_out   = (const float*)d_in[28];
    const float* w_res    = (const float*)d_in[29];
    const float* b_res    = (const float*)d_in[30];

    k_in_mlp<<<NPTS/4, 256>>>(features, w_in1, b_in1, w_in2, b_in2);
    k_stats_part<<<NPART, 256>>>(0);
    k_stats_comb<<<1, 32>>>(0);
    k_qkv<<<NPTS/4, 256>>>(wq, bq, wk, bk, wv, bv, g_in, be_in);
    k_attn<<<NPTS, 256>>>(points, nuv, conv_w1, conv_b1, conv_w2, conv_b2,
                          rls, rbf_a, rbf_b, rbf_c);
    k_out_mlp<<<NPTS/4, 256>>>(w_o1, b_o1, w_o2, b_o2);
    k_stats_part<<<NPART, 256>>>(1);
    k_stats_comb<<<1, 32>>>(1);
    k_finalize<<<NPTS*64/256, 256>>>(features, g_out, be_out, w_res, b_res, (float*)d_out);
}